// round 11
// baseline (speedup 1.0000x reference)
#include <cuda_runtime.h>
#include <cuda_fp16.h>
#include <cstdint>
#include <cstddef>

// Problem constants (fixed by dataset)
#define T_TOT 131072
#define CDIM  512
#define NF    1024   // interleaved [y_0,z_0,y_1,z_1,...]  (y=W1 path, z=W2W1 path)
#define BATCH 128

// tcgen05 requires the sm_103a ("arch-accelerated") target pass.
#if defined(__CUDA_ARCH_FEAT_SM103_ALL)
#define HAS_TC 1
#else
#define HAS_TC 0
#endif

// ---------------- scratch: __device__ globals (no allocation allowed) ----------------
// Tiled + pre-swizzled layouts (16/32 KB blocks = smem images for cp.async.bulk):
// A block (row-tile R of 256 rows, K-chunk c): base=(R*8+c)*32768, two 16 KB
//   sub-halves of 128 rows each.
// B block (icol-tile nt of 256, K-chunk c): base=(nt*8+c)*32768; first 16 KB =
//   icols rloc 0..127, second 16 KB = rloc 128..255 (swizzle local to each half).
__device__ __half g_x[(size_t)T_TOT * CDIM];     // LN output fp16, tiled    134 MB
__device__ __half g_wcat[(size_t)NF * CDIM];     // interleaved weights, tiled (1 MB)
__device__ float  g_bcat[NF];                    // interleaved [b1_d ; (W2 b1 + b2)_d]
__device__ float  g_num[BATCH * CDIM];           // Σ w*y per (graph, d)
__device__ float  g_den[BATCH * CDIM];           // Σ w   per (graph, d)

// ---------------- PTX helpers ----------------
__device__ __forceinline__ uint32_t smem_u32(const void* p) {
    return (uint32_t)__cvta_generic_to_shared(p);
}
#define SWZ128(o) ((o) ^ (((o) >> 3) & 0x70))

// ---------------- K1a: W1 row d -> wcat icol 2d (fp16, tiled); zero accumulators ----
__global__ void k_wcopy(const float* __restrict__ W1) {
    int i = blockIdx.x * 256 + threadIdx.x;      // 262144 elements
    int d = i >> 9, k = i & 511;
    int icol = 2 * d;
    int nt = icol >> 8, rloc = icol & 255;
    int c = k >> 6, klocb = (k & 63) * 2;
    size_t base = ((size_t)(nt * 8 + c)) * 32768;
    uint32_t off = SWZ128((uint32_t)(rloc * 128 + klocb));
    *(__half*)((char*)g_wcat + base + off) = __float2half(W1[i]);
    if (i < BATCH * CDIM) { g_num[i] = 0.f; g_den[i] = 0.f; }
}

// ---------------- K1b: bcat interleaved [b1_d ; (W2@b1+b2)_d], warp-per-output ------
__global__ void k_bcat(const float* __restrict__ W2, const float* __restrict__ b1,
                       const float* __restrict__ b2) {
    int w = (blockIdx.x * 256 + threadIdx.x) >> 5;   // 0..511 (grid 64 x 256)
    int lane = threadIdx.x & 31;
    float acc = 0.f;
    const float* row = W2 + (size_t)w * CDIM;
#pragma unroll 4
    for (int j = lane; j < CDIM; j += 32) acc += row[j] * __ldg(&b1[j]);
#pragma unroll
    for (int o = 16; o > 0; o >>= 1) acc += __shfl_xor_sync(0xFFFFFFFFu, acc, o);
    if (lane == 0) {
        g_bcat[2 * w]     = __ldg(&b1[w]);
        g_bcat[2 * w + 1] = acc + __ldg(&b2[w]);
    }
}

// ---------------- K1c: W21 = W2 @ W1 -> wcat icol 2d+1 (fp16, tiled) ----------------
__global__ void __launch_bounds__(256) k_w21(const float* __restrict__ W2,
                                             const float* __restrict__ W1) {
    __shared__ float sA[32][65];
    __shared__ float sB[32][64];
    int t = threadIdx.x;
    int tx = t & 15, ty = t >> 4;
    int d0 = blockIdx.y * 64, k0 = blockIdx.x * 64;
    float acc[4][4] = {};
    for (int jc = 0; jc < CDIM; jc += 32) {
        for (int i = t; i < 64 * 32; i += 256) {
            int r = i >> 5, j = i & 31;
            sA[j][r] = W2[(size_t)(d0 + r) * CDIM + jc + j];
        }
        for (int i = t; i < 32 * 64; i += 256) {
            int j = i >> 6, c = i & 63;
            sB[j][c] = W1[(size_t)(jc + j) * CDIM + k0 + c];
        }
        __syncthreads();
#pragma unroll
        for (int j = 0; j < 32; j++) {
            float a[4], b[4];
#pragma unroll
            for (int i = 0; i < 4; i++) a[i] = sA[j][ty * 4 + i];
#pragma unroll
            for (int l = 0; l < 4; l++) b[l] = sB[j][tx * 4 + l];
#pragma unroll
            for (int i = 0; i < 4; i++)
#pragma unroll
                for (int l = 0; l < 4; l++) acc[i][l] += a[i] * b[l];
        }
        __syncthreads();
    }
#pragma unroll
    for (int i = 0; i < 4; i++)
#pragma unroll
        for (int l = 0; l < 4; l++) {
            int dr = d0 + ty * 4 + i;
            int k  = k0 + tx * 4 + l;
            int icol = 2 * dr + 1;
            int nt = icol >> 8, rloc = icol & 255;
            int c = k >> 6, klocb = (k & 63) * 2;
            size_t base = ((size_t)(nt * 8 + c)) * 32768;
            uint32_t off = SWZ128((uint32_t)(rloc * 128 + klocb));
            *(__half*)((char*)g_wcat + base + off) = __float2half(acc[i][l]);
        }
}

// ---------------- K2: LayerNorm (eps=1e-5) -> fp16 (tiled + pre-swizzled) -----------
__global__ void k_ln(const float* __restrict__ hs, const float* __restrict__ gamma,
                     const float* __restrict__ beta) {
    __shared__ float s_sum[4], s_sq[4];
    int row = blockIdx.x;
    int t = threadIdx.x;                          // 128 threads, 4 floats each
    const float4 v = __ldg((const float4*)(hs + (size_t)row * CDIM) + t);
    float s = v.x + v.y + v.z + v.w;
    float q = v.x * v.x + v.y * v.y + v.z * v.z + v.w * v.w;
#pragma unroll
    for (int o = 16; o > 0; o >>= 1) {
        s += __shfl_xor_sync(0xFFFFFFFFu, s, o);
        q += __shfl_xor_sync(0xFFFFFFFFu, q, o);
    }
    if ((t & 31) == 0) { s_sum[t >> 5] = s; s_sq[t >> 5] = q; }
    __syncthreads();
    s = s_sum[0] + s_sum[1] + s_sum[2] + s_sum[3];
    q = s_sq[0] + s_sq[1] + s_sq[2] + s_sq[3];
    float mu = s * (1.f / CDIM);
    float var = q * (1.f / CDIM) - mu * mu;
    float rs = rsqrtf(var + 1e-5f);
    float4 g4 = __ldg((const float4*)gamma + t);
    float4 b4 = __ldg((const float4*)beta + t);
    __half2 h0 = __floats2half2_rn((v.x - mu) * rs * g4.x + b4.x,
                                   (v.y - mu) * rs * g4.y + b4.y);
    __half2 h1 = __floats2half2_rn((v.z - mu) * rs * g4.z + b4.z,
                                   (v.w - mu) * rs * g4.w + b4.w);
    uint2 packed;
    packed.x = *(uint32_t*)&h0;
    packed.y = *(uint32_t*)&h1;
    int R = row >> 8, sub = (row >> 7) & 1, rloc = row & 127;
    int c = t >> 4;
    int klocb = (8 * t) & 127;
    size_t base = ((size_t)(R * 8 + c)) * 32768 + (size_t)sub * 16384;
    uint32_t off = SWZ128((uint32_t)(rloc * 128 + klocb));
    *(uint2*)((char*)g_x + base + off) = packed;
}

// ============================================================================
// K3: PERSISTENT tcgen05 GEMM + fused softmax-pool epilogue (sm_103a only)
// Grid (8 nt2, 18): 144 persistent CTAs, 1/SM, 288 threads.
// B tile (64 features = 128 icols, full K=512) resident in smem (128 KB).
// Warp 8 = producer: streams A (2-stage bulk-copy), issues M=128 x N=128 MMAs
// into ping-pong TMEM D buffers. Warps 0-7 = consumer: per row-tile epilogue
// (LDTM, exp, segment-scan, atomics) overlapped with next row-tile's MMA.
// ============================================================================
#define SM_BAT    128             // 128 ints
#define SM_EPI    1024            // s_num 128x33 f32 (16896) + s_den (16896) = 33792
#define SM_A      34816           // 2 stages x 16384
#define SM_B      67584           // 8 chunks x 16384 = 131072
#define SM_TOTAL_TC 198656
#define IDESC1 0x8200010u         // f16*f16->f32, M=128, N=128
// mbars: binit@8; aful[2]@16,24; sdone[2]@32,40; mdone[2]@48,56; edone[2]@64,72

#if HAS_TC
__device__ __forceinline__ uint32_t elect_one_pred() {
    uint32_t pred;
    asm volatile("{\n\t.reg .pred p;\n\telect.sync _|p, 0xFFFFFFFF;\n\tselp.b32 %0, 1, 0, p;\n\t}"
                 : "=r"(pred));
    return pred;
}
static constexpr uint64_t SMEM_DESC_BASE_SW128 =
    (uint64_t(2) << 61) | (uint64_t(1) << 46) | (uint64_t(64) << 32) | (uint64_t(1) << 16);
#define MAKE_SMEM_DESC(b) (SMEM_DESC_BASE_SW128 | ((uint64_t)((b) >> 4) & 0x3FFF))
#define MBARRIER_INIT(a, c) \
    asm volatile("mbarrier.init.shared.b64 [%0], %1;" :: "r"(a), "r"(c) : "memory")
#define MBAR_EXPECT_TX(a, n) \
    asm volatile("mbarrier.arrive.expect_tx.shared.b64 _, [%0], %1;" :: "r"(a), "r"(n) : "memory")
#define MBAR_ARRIVE(a) \
    asm volatile("mbarrier.arrive.shared.b64 _, [%0];" :: "r"(a) : "memory")
#define MBAR_WAIT(a, ph) do {                                                  \
    asm volatile("{\n\t.reg .pred P1;\n\t"                                     \
        "WL_%=:\n\t"                                                           \
        "mbarrier.try_wait.parity.acquire.cta.shared::cta.b64 P1, [%0], %1, 0x989680;\n\t" \
        "@P1 bra.uni WD_%=;\n\t"                                               \
        "bra.uni WL_%=;\n\t"                                                   \
        "WD_%=:\n\t}" :: "r"(a), "r"(ph) : "memory");                          \
} while (0)
#define BULK_CP(dst, src, n, mbar) \
    asm volatile("cp.async.bulk.shared::cta.global.mbarrier::complete_tx::bytes " \
                 "[%0], [%1], %2, [%3];" \
                 :: "r"(dst), "l"(src), "r"(n), "r"(mbar) : "memory")
__device__ __forceinline__ void mma_f16_ss(uint32_t d_tmem, uint64_t a_desc, uint64_t b_desc,
                                           uint32_t idesc, uint32_t en) {
    uint32_t z = 0;
    asm volatile(
        "{\n\t.reg .pred p;\n\t"
        "setp.ne.u32 p, %5, 0;\n\t"
        "tcgen05.mma.cta_group::1.kind::f16 [%0], %1, %2, %3, {%4, %4, %4, %4}, p;\n\t"
        "}"
        :: "r"(d_tmem), "l"(a_desc), "l"(b_desc), "r"(idesc), "r"(z), "r"(en)
        : "memory");
}
#define LDTM_X32(r, a) \
    asm volatile( \
        "tcgen05.ld.sync.aligned.32x32b.x32.b32 " \
        "{%0, %1, %2, %3, %4, %5, %6, %7, " \
        " %8, %9, %10, %11, %12, %13, %14, %15, " \
        " %16, %17, %18, %19, %20, %21, %22, %23, " \
        " %24, %25, %26, %27, %28, %29, %30, %31}, [%32];" \
        : "=r"((r)[0]),  "=r"((r)[1]),  "=r"((r)[2]),  "=r"((r)[3]), \
          "=r"((r)[4]),  "=r"((r)[5]),  "=r"((r)[6]),  "=r"((r)[7]), \
          "=r"((r)[8]),  "=r"((r)[9]),  "=r"((r)[10]), "=r"((r)[11]), \
          "=r"((r)[12]), "=r"((r)[13]), "=r"((r)[14]), "=r"((r)[15]), \
          "=r"((r)[16]), "=r"((r)[17]), "=r"((r)[18]), "=r"((r)[19]), \
          "=r"((r)[20]), "=r"((r)[21]), "=r"((r)[22]), "=r"((r)[23]), \
          "=r"((r)[24]), "=r"((r)[25]), "=r"((r)[26]), "=r"((r)[27]), \
          "=r"((r)[28]), "=r"((r)[29]), "=r"((r)[30]), "=r"((r)[31]) \
        : "r"(a))
#endif // HAS_TC

__global__ void __launch_bounds__(288, 1) k_gemm_tc(const int* __restrict__ batch) {
#if HAS_TC
    extern __shared__ char sm[];
    const uint32_t smb = smem_u32(sm);
    const int tid = threadIdx.x;
    const int lane = tid & 31, wid = tid >> 5;
    const int nt2 = blockIdx.x;                // 64-feature tile (0..7)
    const int ci  = blockIdx.y;                // persistent-CTA slot (0..17)
    const int nrt = (1024 - ci + 17) / 18;     // row-tiles this CTA owns
    int* s_bat = (int*)(sm + SM_BAT);

    if (wid == 8) {
        asm volatile("tcgen05.alloc.cta_group::1.sync.aligned.shared::cta.b32 [%0], %1;"
                     :: "r"(smb), "r"(256) : "memory");
        asm volatile("tcgen05.relinquish_alloc_permit.cta_group::1.sync.aligned;");
    }
    if (tid == 0) {
        MBARRIER_INIT(smb + 8, 1);                         // binit
#pragma unroll
        for (int s = 0; s < 2; s++) {
            MBARRIER_INIT(smb + 16 + s * 8, 1);            // aful
            MBARRIER_INIT(smb + 32 + s * 8, 1);            // sdone
            MBARRIER_INIT(smb + 48 + s * 8, 1);            // mdone
            MBARRIER_INIT(smb + 64 + s * 8, 256);          // edone
        }
    }
    __syncthreads();
    uint32_t tmem;
    asm volatile("ld.shared.b32 %0, [%1];" : "=r"(tmem) : "r"(smb));

    if (wid == 8) {
        // ======== PRODUCER ========
        const uint32_t ep = elect_one_pred();
        // B tile for nt2: 8 chunks x 16 KB from g_wcat's (nt2>>1) block, half (nt2&1).
        const char* Bsrc = (const char*)g_wcat + (size_t)(nt2 >> 1) * 262144
                                               + (size_t)(nt2 & 1) * 16384;
        const int G = nrt * 8;
        if (ep) {
            MBAR_EXPECT_TX(smb + 8, 131072u);
#pragma unroll
            for (int c = 0; c < 8; c++)
                BULK_CP(smb + SM_B + c * 16384, Bsrc + (size_t)c * 32768, 16384u, smb + 8);
            // A prologue: g = 0,1 (row-tile ci, chunks 0,1)
#pragma unroll
            for (int s = 0; s < 2; s++) {
                MBAR_EXPECT_TX(smb + 16 + s * 8, 16384u);
                BULK_CP(smb + SM_A + s * 16384,
                        (const char*)g_x + (size_t)(ci >> 1) * 262144
                                         + (size_t)(ci & 1) * 16384 + (size_t)s * 32768,
                        16384u, smb + 16 + s * 8);
            }
        }
        MBAR_WAIT(smb + 8, 0);                             // B resident
        for (int g = 0; g < G; g++) {
            const int i = g >> 3, c = g & 7, s = g & 1, buf = i & 1;
            MBAR_WAIT(smb + 16 + s * 8, (g >> 1) & 1);     // A chunk ready
            if (c == 0 && i >= 2)
                MBAR_WAIT(smb + 64 + buf * 8, ((i >> 1) - 1) & 1);  // D[buf] consumed
            if (ep) {
                uint64_t dA = MAKE_SMEM_DESC(smb + SM_A + s * 16384);
                uint64_t dB = MAKE_SMEM_DESC(smb + SM_B + c * 16384);
#pragma unroll
                for (int ks = 0; ks < 4; ks++) {
                    uint32_t en = (c > 0 || ks > 0) ? 1u : 0u;
                    mma_f16_ss(tmem + buf * 128, dA + ks * 2, dB + ks * 2, IDESC1, en);
                }
                asm volatile("tcgen05.commit.cta_group::1.mbarrier::arrive::one.shared::cluster.b64 [%0];"
                             :: "r"(smb + 32 + s * 8) : "memory");
                if (c == 7)
                    asm volatile("tcgen05.commit.cta_group::1.mbarrier::arrive::one.shared::cluster.b64 [%0];"
                                 :: "r"(smb + 48 + buf * 8) : "memory");
            }
            if (g + 2 < G) {
                MBAR_WAIT(smb + 32 + s * 8, (g >> 1) & 1); // MMA done with stage s
                if (ep) {
                    const int g2 = g + 2, i2 = g2 >> 3, c2 = g2 & 7;
                    const int rt2 = ci + 18 * i2;
                    MBAR_EXPECT_TX(smb + 16 + s * 8, 16384u);
                    BULK_CP(smb + SM_A + s * 16384,
                            (const char*)g_x + (size_t)(rt2 >> 1) * 262144
                                             + (size_t)(rt2 & 1) * 16384 + (size_t)c2 * 32768,
                            16384u, smb + 16 + s * 8);
                }
            }
        }
    } else {
        // ======== CONSUMER (warps 0-7, 256 threads) ========
        const int wg = wid >> 2;                   // warpgroup 0/1 -> feature half
        float* s_num = (float*)(sm + SM_EPI);
        float* s_den = s_num + 128 * 33;
        const int rloc = (wid & 3) * 32 + lane;    // row within 128
        const int j = tid & 31, gscan = tid >> 5;  // scan: feature slot, row-group
        for (int i = 0; i < nrt; i++) {
            const int buf = i & 1;
            const int rt = ci + 18 * i;
            const int row0 = rt * 128;
            if (tid < 128) s_bat[tid] = __ldg(&batch[row0 + tid]);
            MBAR_WAIT(smb + 48 + buf * 8, (i >> 1) & 1);   // MMAs for this tile done
            asm volatile("tcgen05.fence::after_thread_sync;" ::: "memory");
#pragma unroll 1
            for (int p = 0; p < 2; p++) {          // 16 features per wg per pass
                uint32_t rr[32];
                LDTM_X32(rr, tmem + buf * 128 + wg * 64 + p * 32);
                asm volatile("tcgen05.wait::ld.sync.aligned;" ::: "memory");
#pragma unroll
                for (int i2 = 0; i2 < 16; i2++) {
                    const int icg = nt2 * 128 + 2 * (wg * 32 + p * 16 + i2);
                    float y = __uint_as_float(rr[2 * i2])     + __ldg(&g_bcat[icg]);
                    float z = __uint_as_float(rr[2 * i2 + 1]) + __ldg(&g_bcat[icg + 1]);
                    float w = __expf(z);
                    s_num[rloc * 33 + wg * 16 + i2] = w * y;
                    s_den[rloc * 33 + wg * 16 + i2] = w;
                }
                asm volatile("bar.sync 1, 256;" ::: "memory");
                {   // scan: 32 feature-slots x 8 groups of 16 rows
                    const int dglob = nt2 * 64 + (j >> 4) * 32 + p * 16 + (j & 15);
                    float an = 0.f, ad = 0.f;
                    int curb = s_bat[gscan * 16];
#pragma unroll 4
                    for (int r = 0; r < 16; r++) {
                        const int rr2 = gscan * 16 + r;
                        const int bb = s_bat[rr2];
                        if (bb != curb) {
                            atomicAdd(&g_num[curb * CDIM + dglob], an);
                            atomicAdd(&g_den[curb * CDIM + dglob], ad);
                            an = 0.f; ad = 0.f; curb = bb;
                        }
                        an += s_num[rr2 * 33 + j];
                        ad += s_den[rr2 * 33 + j];
                    }
                    atomicAdd(&g_num[curb * CDIM + dglob], an);
                    atomicAdd(&g_den[curb * CDIM + dglob], ad);
                }
                asm volatile("bar.sync 1, 256;" ::: "memory");
            }
            asm volatile("tcgen05.fence::before_thread_sync;" ::: "memory");
            MBAR_ARRIVE(smb + 64 + buf * 8);       // D[buf] free for producer
        }
    }
    __syncthreads();
    if (wid == 8)
        asm volatile("tcgen05.dealloc.cta_group::1.sync.aligned.b32 %0, %1;" :: "r"(tmem), "r"(256));
#endif // HAS_TC
}

// ---------------- K4: finalize out = num / den ----------------
__global__ void k_final(float* __restrict__ out) {
    int i = blockIdx.x * 512 + threadIdx.x;
    float den = g_den[i];
    out[i] = (den > 0.f) ? (g_num[i] / den) : 0.f;
}

// ---------------- host launcher ----------------
extern "C" void kernel_launch(void* const* d_in, const int* in_sizes, int n_in,
                              void* d_out, int out_size) {
    const float* hs    = (const float*)d_in[0];
    const int*   batch = (const int*)d_in[1];
    // d_in[2] = max_nodes (unused)
    const float* gamma = (const float*)d_in[3];
    const float* beta  = (const float*)d_in[4];
    const float* W1    = (const float*)d_in[5];
    const float* b1    = (const float*)d_in[6];
    const float* W2    = (const float*)d_in[7];
    const float* b2    = (const float*)d_in[8];
    float* out = (float*)d_out;

    cudaFuncSetAttribute(k_gemm_tc, cudaFuncAttributeMaxDynamicSharedMemorySize, SM_TOTAL_TC);

    k_wcopy<<<1024, 256>>>(W1);
    k_bcat<<<64, 256>>>(W2, b1, b2);
    dim3 wg(8, 8);
    k_w21<<<wg, 256>>>(W2, W1);
    k_ln<<<T_TOT, 128>>>(hs, gamma, beta);
    dim3 gtc(8, 18);
    k_gemm_tc<<<gtc, 288, SM_TOTAL_TC>>>(batch);
    k_final<<<128, 512>>>(out);
}

// round 12
// speedup vs baseline: 1.1612x; 1.1612x over previous
#include <cuda_runtime.h>
#include <cuda_fp16.h>
#include <cstdint>
#include <cstddef>

// Problem constants (fixed by dataset)
#define T_TOT 131072
#define CDIM  512
#define NF    1024   // interleaved [y_0,z_0,y_1,z_1,...]  (y=W1 path, z=W2W1 path)
#define BATCH 128

// tcgen05 requires the sm_103a ("arch-accelerated") target pass.
#if defined(__CUDA_ARCH_FEAT_SM103_ALL)
#define HAS_TC 1
#else
#define HAS_TC 0
#endif

// ---------------- scratch: __device__ globals (no allocation allowed) ----------------
// Tiled + pre-swizzled layouts (16/32 KB blocks = smem images for cp.async.bulk):
// A block (row-tile R of 256 rows, K-chunk c): base=(R*8+c)*32768, two 16 KB
//   sub-halves of 128 rows each.
// B block (icol-tile nt of 256, K-chunk c): base=(nt*8+c)*32768; first 16 KB =
//   icols rloc 0..127, second 16 KB = rloc 128..255 (swizzle local to each half).
__device__ __half g_x[(size_t)T_TOT * CDIM];     // LN output fp16, tiled    134 MB
__device__ __half g_wcat[(size_t)NF * CDIM];     // interleaved weights, tiled (1 MB)
__device__ float  g_bcat[NF];                    // interleaved [b1_d ; (W2 b1 + b2)_d]
__device__ float  g_num[BATCH * CDIM];           // Σ w*y per (graph, d)
__device__ float  g_den[BATCH * CDIM];           // Σ w   per (graph, d)

// ---------------- PTX helpers ----------------
__device__ __forceinline__ uint32_t smem_u32(const void* p) {
    return (uint32_t)__cvta_generic_to_shared(p);
}
#define SWZ128(o) ((o) ^ (((o) >> 3) & 0x70))

// ---------------- K1a: W1 row d -> wcat icol 2d (fp16, tiled); zero accumulators ----
__global__ void k_wcopy(const float* __restrict__ W1) {
    int i = blockIdx.x * 256 + threadIdx.x;      // 262144 elements
    int d = i >> 9, k = i & 511;
    int icol = 2 * d;
    int nt = icol >> 8, rloc = icol & 255;
    int c = k >> 6, klocb = (k & 63) * 2;
    size_t base = ((size_t)(nt * 8 + c)) * 32768;
    uint32_t off = SWZ128((uint32_t)(rloc * 128 + klocb));
    *(__half*)((char*)g_wcat + base + off) = __float2half(W1[i]);
    if (i < BATCH * CDIM) { g_num[i] = 0.f; g_den[i] = 0.f; }
}

// ---------------- K1b: bcat interleaved [b1_d ; (W2@b1+b2)_d], warp-per-output ------
__global__ void k_bcat(const float* __restrict__ W2, const float* __restrict__ b1,
                       const float* __restrict__ b2) {
    int w = (blockIdx.x * 256 + threadIdx.x) >> 5;   // 0..511 (grid 64 x 256)
    int lane = threadIdx.x & 31;
    float acc = 0.f;
    const float* row = W2 + (size_t)w * CDIM;
#pragma unroll 4
    for (int j = lane; j < CDIM; j += 32) acc += row[j] * __ldg(&b1[j]);
#pragma unroll
    for (int o = 16; o > 0; o >>= 1) acc += __shfl_xor_sync(0xFFFFFFFFu, acc, o);
    if (lane == 0) {
        g_bcat[2 * w]     = __ldg(&b1[w]);
        g_bcat[2 * w + 1] = acc + __ldg(&b2[w]);
    }
}

// ---------------- K1c: W21 = W2 @ W1 -> wcat icol 2d+1 (fp16, tiled) ----------------
__global__ void __launch_bounds__(256) k_w21(const float* __restrict__ W2,
                                             const float* __restrict__ W1) {
    __shared__ float sA[32][65];
    __shared__ float sB[32][64];
    int t = threadIdx.x;
    int tx = t & 15, ty = t >> 4;
    int d0 = blockIdx.y * 64, k0 = blockIdx.x * 64;
    float acc[4][4] = {};
    for (int jc = 0; jc < CDIM; jc += 32) {
        for (int i = t; i < 64 * 32; i += 256) {
            int r = i >> 5, j = i & 31;
            sA[j][r] = W2[(size_t)(d0 + r) * CDIM + jc + j];
        }
        for (int i = t; i < 32 * 64; i += 256) {
            int j = i >> 6, c = i & 63;
            sB[j][c] = W1[(size_t)(jc + j) * CDIM + k0 + c];
        }
        __syncthreads();
#pragma unroll
        for (int j = 0; j < 32; j++) {
            float a[4], b[4];
#pragma unroll
            for (int i = 0; i < 4; i++) a[i] = sA[j][ty * 4 + i];
#pragma unroll
            for (int l = 0; l < 4; l++) b[l] = sB[j][tx * 4 + l];
#pragma unroll
            for (int i = 0; i < 4; i++)
#pragma unroll
                for (int l = 0; l < 4; l++) acc[i][l] += a[i] * b[l];
        }
        __syncthreads();
    }
#pragma unroll
    for (int i = 0; i < 4; i++)
#pragma unroll
        for (int l = 0; l < 4; l++) {
            int dr = d0 + ty * 4 + i;
            int k  = k0 + tx * 4 + l;
            int icol = 2 * dr + 1;
            int nt = icol >> 8, rloc = icol & 255;
            int c = k >> 6, klocb = (k & 63) * 2;
            size_t base = ((size_t)(nt * 8 + c)) * 32768;
            uint32_t off = SWZ128((uint32_t)(rloc * 128 + klocb));
            *(__half*)((char*)g_wcat + base + off) = __float2half(acc[i][l]);
        }
}

// ---------------- K2: LayerNorm (eps=1e-5) -> fp16 (tiled + pre-swizzled) -----------
__global__ void k_ln(const float* __restrict__ hs, const float* __restrict__ gamma,
                     const float* __restrict__ beta) {
    __shared__ float s_sum[4], s_sq[4];
    int row = blockIdx.x;
    int t = threadIdx.x;                          // 128 threads, 4 floats each
    const float4 v = __ldg((const float4*)(hs + (size_t)row * CDIM) + t);
    float s = v.x + v.y + v.z + v.w;
    float q = v.x * v.x + v.y * v.y + v.z * v.z + v.w * v.w;
#pragma unroll
    for (int o = 16; o > 0; o >>= 1) {
        s += __shfl_xor_sync(0xFFFFFFFFu, s, o);
        q += __shfl_xor_sync(0xFFFFFFFFu, q, o);
    }
    if ((t & 31) == 0) { s_sum[t >> 5] = s; s_sq[t >> 5] = q; }
    __syncthreads();
    s = s_sum[0] + s_sum[1] + s_sum[2] + s_sum[3];
    q = s_sq[0] + s_sq[1] + s_sq[2] + s_sq[3];
    float mu = s * (1.f / CDIM);
    float var = q * (1.f / CDIM) - mu * mu;
    float rs = rsqrtf(var + 1e-5f);
    float4 g4 = __ldg((const float4*)gamma + t);
    float4 b4 = __ldg((const float4*)beta + t);
    __half2 h0 = __floats2half2_rn((v.x - mu) * rs * g4.x + b4.x,
                                   (v.y - mu) * rs * g4.y + b4.y);
    __half2 h1 = __floats2half2_rn((v.z - mu) * rs * g4.z + b4.z,
                                   (v.w - mu) * rs * g4.w + b4.w);
    uint2 packed;
    packed.x = *(uint32_t*)&h0;
    packed.y = *(uint32_t*)&h1;
    int R = row >> 8, sub = (row >> 7) & 1, rloc = row & 127;
    int c = t >> 4;
    int klocb = (8 * t) & 127;
    size_t base = ((size_t)(R * 8 + c)) * 32768 + (size_t)sub * 16384;
    uint32_t off = SWZ128((uint32_t)(rloc * 128 + klocb));
    *(uint2*)((char*)g_x + base + off) = packed;
}

// ============================================================================
// K3: PERSISTENT tcgen05 GEMM + fused softmax-pool epilogue (sm_103a only)
// Grid (8 nt2, 18): 144 persistent CTAs, 1/SM, 288 threads.
// B tile (64 features = 128 icols, full K=512) resident in smem (128 KB).
// Warp 8 = producer: streams A via FOUR 16 KB bulk-copy stages (64 KB MLP),
// issues M=128 x N=128 MMAs into ping-pong TMEM D buffers. Warps 0-7 =
// consumer: per row-tile epilogue overlapped with next row-tile's MMA.
// ============================================================================
#define SM_BAT    128             // 128 ints @ 128..640
#define SM_EPI    1024            // s_num 128x33 f32 (16896) + s_den (16896) = 33792
#define SM_A      34816           // 4 stages x 16384 = 65536
#define SM_B      100352          // 8 chunks x 16384 = 131072 -> ends 231424
#define SM_TOTAL_TC 231424
#define IDESC1 0x8200010u         // f16*f16->f32, M=128, N=128
// mbars: binit@8; aful[4]@16..40; sdone[4]@48..72; mdone[2]@80,88; edone[2]@96,104

#if HAS_TC
__device__ __forceinline__ uint32_t elect_one_pred() {
    uint32_t pred;
    asm volatile("{\n\t.reg .pred p;\n\telect.sync _|p, 0xFFFFFFFF;\n\tselp.b32 %0, 1, 0, p;\n\t}"
                 : "=r"(pred));
    return pred;
}
static constexpr uint64_t SMEM_DESC_BASE_SW128 =
    (uint64_t(2) << 61) | (uint64_t(1) << 46) | (uint64_t(64) << 32) | (uint64_t(1) << 16);
#define MAKE_SMEM_DESC(b) (SMEM_DESC_BASE_SW128 | ((uint64_t)((b) >> 4) & 0x3FFF))
#define MBARRIER_INIT(a, c) \
    asm volatile("mbarrier.init.shared.b64 [%0], %1;" :: "r"(a), "r"(c) : "memory")
#define MBAR_EXPECT_TX(a, n) \
    asm volatile("mbarrier.arrive.expect_tx.shared.b64 _, [%0], %1;" :: "r"(a), "r"(n) : "memory")
#define MBAR_ARRIVE(a) \
    asm volatile("mbarrier.arrive.shared.b64 _, [%0];" :: "r"(a) : "memory")
#define MBAR_WAIT(a, ph) do {                                                  \
    asm volatile("{\n\t.reg .pred P1;\n\t"                                     \
        "WL_%=:\n\t"                                                           \
        "mbarrier.try_wait.parity.acquire.cta.shared::cta.b64 P1, [%0], %1, 0x989680;\n\t" \
        "@P1 bra.uni WD_%=;\n\t"                                               \
        "bra.uni WL_%=;\n\t"                                                   \
        "WD_%=:\n\t}" :: "r"(a), "r"(ph) : "memory");                          \
} while (0)
#define BULK_CP(dst, src, n, mbar) \
    asm volatile("cp.async.bulk.shared::cta.global.mbarrier::complete_tx::bytes " \
                 "[%0], [%1], %2, [%3];" \
                 :: "r"(dst), "l"(src), "r"(n), "r"(mbar) : "memory")
__device__ __forceinline__ void mma_f16_ss(uint32_t d_tmem, uint64_t a_desc, uint64_t b_desc,
                                           uint32_t idesc, uint32_t en) {
    uint32_t z = 0;
    asm volatile(
        "{\n\t.reg .pred p;\n\t"
        "setp.ne.u32 p, %5, 0;\n\t"
        "tcgen05.mma.cta_group::1.kind::f16 [%0], %1, %2, %3, {%4, %4, %4, %4}, p;\n\t"
        "}"
        :: "r"(d_tmem), "l"(a_desc), "l"(b_desc), "r"(idesc), "r"(z), "r"(en)
        : "memory");
}
#define LDTM_X32(r, a) \
    asm volatile( \
        "tcgen05.ld.sync.aligned.32x32b.x32.b32 " \
        "{%0, %1, %2, %3, %4, %5, %6, %7, " \
        " %8, %9, %10, %11, %12, %13, %14, %15, " \
        " %16, %17, %18, %19, %20, %21, %22, %23, " \
        " %24, %25, %26, %27, %28, %29, %30, %31}, [%32];" \
        : "=r"((r)[0]),  "=r"((r)[1]),  "=r"((r)[2]),  "=r"((r)[3]), \
          "=r"((r)[4]),  "=r"((r)[5]),  "=r"((r)[6]),  "=r"((r)[7]), \
          "=r"((r)[8]),  "=r"((r)[9]),  "=r"((r)[10]), "=r"((r)[11]), \
          "=r"((r)[12]), "=r"((r)[13]), "=r"((r)[14]), "=r"((r)[15]), \
          "=r"((r)[16]), "=r"((r)[17]), "=r"((r)[18]), "=r"((r)[19]), \
          "=r"((r)[20]), "=r"((r)[21]), "=r"((r)[22]), "=r"((r)[23]), \
          "=r"((r)[24]), "=r"((r)[25]), "=r"((r)[26]), "=r"((r)[27]), \
          "=r"((r)[28]), "=r"((r)[29]), "=r"((r)[30]), "=r"((r)[31]) \
        : "r"(a))
#endif // HAS_TC

__global__ void __launch_bounds__(288, 1) k_gemm_tc(const int* __restrict__ batch) {
#if HAS_TC
    extern __shared__ char sm[];
    const uint32_t smb = smem_u32(sm);
    const int tid = threadIdx.x;
    const int lane = tid & 31, wid = tid >> 5;
    const int nt2 = blockIdx.x;                // 64-feature tile (0..7)
    const int ci  = blockIdx.y;                // persistent-CTA slot (0..17)
    const int nrt = (1024 - ci + 17) / 18;     // row-tiles this CTA owns
    int* s_bat = (int*)(sm + SM_BAT);

    if (wid == 8) {
        asm volatile("tcgen05.alloc.cta_group::1.sync.aligned.shared::cta.b32 [%0], %1;"
                     :: "r"(smb), "r"(256) : "memory");
        asm volatile("tcgen05.relinquish_alloc_permit.cta_group::1.sync.aligned;");
    }
    if (tid == 0) {
        MBARRIER_INIT(smb + 8, 1);                         // binit
#pragma unroll
        for (int s = 0; s < 4; s++) {
            MBARRIER_INIT(smb + 16 + s * 8, 1);            // aful[4]
            MBARRIER_INIT(smb + 48 + s * 8, 1);            // sdone[4]
        }
#pragma unroll
        for (int b = 0; b < 2; b++) {
            MBARRIER_INIT(smb + 80 + b * 8, 1);            // mdone[2]
            MBARRIER_INIT(smb + 96 + b * 8, 256);          // edone[2]
        }
    }
    __syncthreads();
    uint32_t tmem;
    asm volatile("ld.shared.b32 %0, [%1];" : "=r"(tmem) : "r"(smb));

    if (wid == 8) {
        // ======== PRODUCER ========
        const uint32_t ep = elect_one_pred();
        // B tile for nt2: 8 chunks x 16 KB from g_wcat's (nt2>>1) block, half (nt2&1).
        const char* Bsrc = (const char*)g_wcat + (size_t)(nt2 >> 1) * 262144
                                               + (size_t)(nt2 & 1) * 16384;
        const int G = nrt * 8;
        auto a_src = [&](int g) -> const char* {
            const int i = g >> 3, c = g & 7;
            const int rt = ci + 18 * i;
            return (const char*)g_x + (size_t)(rt >> 1) * 262144
                                    + (size_t)(rt & 1) * 16384 + (size_t)c * 32768;
        };
        if (ep) {
            MBAR_EXPECT_TX(smb + 8, 131072u);
#pragma unroll
            for (int c = 0; c < 8; c++)
                BULK_CP(smb + SM_B + c * 16384, Bsrc + (size_t)c * 32768, 16384u, smb + 8);
            // A prologue: g = 0..3 into stages 0..3
#pragma unroll
            for (int s = 0; s < 4; s++) {
                MBAR_EXPECT_TX(smb + 16 + s * 8, 16384u);
                BULK_CP(smb + SM_A + s * 16384, a_src(s), 16384u, smb + 16 + s * 8);
            }
        }
        MBAR_WAIT(smb + 8, 0);                             // B resident
        for (int g = 0; g < G; g++) {
            const int i = g >> 3, c = g & 7, s = g & 3, buf = i & 1;
            const int ph = (g >> 2) & 1;
            MBAR_WAIT(smb + 16 + s * 8, ph);               // A chunk ready
            if (c == 0 && i >= 2)
                MBAR_WAIT(smb + 96 + buf * 8, ((i >> 1) - 1) & 1);  // D[buf] consumed
            if (ep) {
                uint64_t dA = MAKE_SMEM_DESC(smb + SM_A + s * 16384);
                uint64_t dB = MAKE_SMEM_DESC(smb + SM_B + c * 16384);
#pragma unroll
                for (int ks = 0; ks < 4; ks++) {
                    uint32_t en = (c > 0 || ks > 0) ? 1u : 0u;
                    mma_f16_ss(tmem + buf * 128, dA + ks * 2, dB + ks * 2, IDESC1, en);
                }
                asm volatile("tcgen05.commit.cta_group::1.mbarrier::arrive::one.shared::cluster.b64 [%0];"
                             :: "r"(smb + 48 + s * 8) : "memory");
                if (c == 7)
                    asm volatile("tcgen05.commit.cta_group::1.mbarrier::arrive::one.shared::cluster.b64 [%0];"
                                 :: "r"(smb + 80 + buf * 8) : "memory");
            }
            if (g + 4 < G) {
                MBAR_WAIT(smb + 48 + s * 8, ph);           // MMA done with stage s
                if (ep) {
                    MBAR_EXPECT_TX(smb + 16 + s * 8, 16384u);
                    BULK_CP(smb + SM_A + s * 16384, a_src(g + 4), 16384u, smb + 16 + s * 8);
                }
            }
        }
    } else {
        // ======== CONSUMER (warps 0-7, 256 threads) ========
        const int wg = wid >> 2;                   // warpgroup 0/1 -> feature half
        float* s_num = (float*)(sm + SM_EPI);
        float* s_den = s_num + 128 * 33;
        const int rloc = (wid & 3) * 32 + lane;    // row within 128
        const int j = tid & 31, gscan = tid >> 5;  // scan: feature slot, row-group
        for (int i = 0; i < nrt; i++) {
            const int buf = i & 1;
            const int rt = ci + 18 * i;
            const int row0 = rt * 128;
            if (tid < 128) s_bat[tid] = __ldg(&batch[row0 + tid]);
            MBAR_WAIT(smb + 80 + buf * 8, (i >> 1) & 1);   // MMAs for this tile done
            asm volatile("tcgen05.fence::after_thread_sync;" ::: "memory");
#pragma unroll 1
            for (int p = 0; p < 2; p++) {          // 16 features per wg per pass
                uint32_t rr[32];
                LDTM_X32(rr, tmem + buf * 128 + wg * 64 + p * 32);
                asm volatile("tcgen05.wait::ld.sync.aligned;" ::: "memory");
#pragma unroll
                for (int i2 = 0; i2 < 16; i2++) {
                    const int icg = nt2 * 128 + 2 * (wg * 32 + p * 16 + i2);
                    float y = __uint_as_float(rr[2 * i2])     + __ldg(&g_bcat[icg]);
                    float z = __uint_as_float(rr[2 * i2 + 1]) + __ldg(&g_bcat[icg + 1]);
                    float w = __expf(z);
                    s_num[rloc * 33 + wg * 16 + i2] = w * y;
                    s_den[rloc * 33 + wg * 16 + i2] = w;
                }
                asm volatile("bar.sync 1, 256;" ::: "memory");
                {   // scan: 32 feature-slots x 8 groups of 16 rows
                    const int dglob = nt2 * 64 + (j >> 4) * 32 + p * 16 + (j & 15);
                    float an = 0.f, ad = 0.f;
                    int curb = s_bat[gscan * 16];
#pragma unroll 4
                    for (int r = 0; r < 16; r++) {
                        const int rr2 = gscan * 16 + r;
                        const int bb = s_bat[rr2];
                        if (bb != curb) {
                            atomicAdd(&g_num[curb * CDIM + dglob], an);
                            atomicAdd(&g_den[curb * CDIM + dglob], ad);
                            an = 0.f; ad = 0.f; curb = bb;
                        }
                        an += s_num[rr2 * 33 + j];
                        ad += s_den[rr2 * 33 + j];
                    }
                    atomicAdd(&g_num[curb * CDIM + dglob], an);
                    atomicAdd(&g_den[curb * CDIM + dglob], ad);
                }
                asm volatile("bar.sync 1, 256;" ::: "memory");
            }
            asm volatile("tcgen05.fence::before_thread_sync;" ::: "memory");
            MBAR_ARRIVE(smb + 96 + buf * 8);       // D[buf] free for producer
        }
    }
    __syncthreads();
    if (wid == 8)
        asm volatile("tcgen05.dealloc.cta_group::1.sync.aligned.b32 %0, %1;" :: "r"(tmem), "r"(256));
#endif // HAS_TC
}

// ---------------- K4: finalize out = num / den ----------------
__global__ void k_final(float* __restrict__ out) {
    int i = blockIdx.x * 512 + threadIdx.x;
    float den = g_den[i];
    out[i] = (den > 0.f) ? (g_num[i] / den) : 0.f;
}

// ---------------- host launcher ----------------
extern "C" void kernel_launch(void* const* d_in, const int* in_sizes, int n_in,
                              void* d_out, int out_size) {
    const float* hs    = (const float*)d_in[0];
    const int*   batch = (const int*)d_in[1];
    // d_in[2] = max_nodes (unused)
    const float* gamma = (const float*)d_in[3];
    const float* beta  = (const float*)d_in[4];
    const float* W1    = (const float*)d_in[5];
    const float* b1    = (const float*)d_in[6];
    const float* W2    = (const float*)d_in[7];
    const float* b2    = (const float*)d_in[8];
    float* out = (float*)d_out;

    cudaFuncSetAttribute(k_gemm_tc, cudaFuncAttributeMaxDynamicSharedMemorySize, SM_TOTAL_TC);

    k_wcopy<<<1024, 256>>>(W1);
    k_bcat<<<64, 256>>>(W2, b1, b2);
    dim3 wg(8, 8);
    k_w21<<<wg, 256>>>(W2, W1);
    k_ln<<<T_TOT, 128>>>(hs, gamma, beta);
    dim3 gtc(8, 18);
    k_gemm_tc<<<gtc, 288, SM_TOTAL_TC>>>(batch);
    k_final<<<128, 512>>>(out);
}